// round 2
// baseline (speedup 1.0000x reference)
#include <cuda_runtime.h>

// SeparateLoss: mean over the N x N cosine-similarity matrix masked by
// label inequality. Binary labels => (2/N^2) * dot(S0, S1),
// Sk = sum of L2-normalized feature rows with label k.
//
// feat [4, 64, 128, 128] f32, label [4, 1, 128, 128] i32.
// Nearest 128->64 picks even indices. N = 16384, C = 64.

#define B 4
#define C 64
#define H 128
#define W 128
#define X 64                       // output spatial size
#define NBLK (B * X)               // 256 pass-1 blocks
#define NSLOT (2 * C)              // 128 accumulation slots (class, channel)
#define NTOT 16384.0f

// slot-major: g_partial[slot * NBLK + blk], slot = class*64 + ch.
// Every element rewritten each launch => deterministic, no zeroing needed.
__device__ float g_partial[NSLOT * NBLK];

__global__ void __launch_bounds__(256) separate_pass1(
    const float* __restrict__ feat, const int* __restrict__ label)
{
    __shared__ float sm[C * 65];   // [ch][xi], padded stride
    __shared__ float invn[X];
    __shared__ int   lab[X];

    const int b   = blockIdx.y;
    const int yi  = blockIdx.x;
    const int y   = yi * 2;        // nearest source row
    const int tid = threadIdx.x;
    const int blk = b * X + yi;

    const float* fb = feat + (size_t)b * C * H * W + (size_t)y * W;

    // Stage tile via float4 (x = 2*xi and 2*xi+1 packed; keep .x/.z).
    // C*32 float4 loads = 2048, 8 per thread.
    #pragma unroll
    for (int i = tid; i < C * (W / 4); i += 256) {
        const int ch = i >> 5;
        const int xj = i & 31;
        const float4 v = reinterpret_cast<const float4*>(fb + (size_t)ch * (H * W))[xj];
        sm[ch * 65 + 2 * xj]     = v.x;
        sm[ch * 65 + 2 * xj + 1] = v.z;
    }
    if (tid < X) lab[tid] = label[b * (H * W) + y * W + tid * 2];
    __syncthreads();

    // Inverse norms: 4 lanes per position, 16 channels each, quad shfl-reduce.
    {
        const int xi = tid >> 2;
        const int q  = tid & 3;
        float s = 0.f;
        #pragma unroll
        for (int k = 0; k < 16; k++) {
            const float v = sm[(q * 16 + k) * 65 + xi];
            s += v * v;
        }
        s += __shfl_xor_sync(0xffffffffu, s, 1);
        s += __shfl_xor_sync(0xffffffffu, s, 2);
        if (q == 0) invn[xi] = 1.0f / fmaxf(sqrtf(s), 1e-12f);
    }
    __syncthreads();

    // Class sums: 4 lanes per channel, 16 positions each, quad shfl-reduce.
    {
        const int ch  = tid >> 2;
        const int sub = tid & 3;
        float s0 = 0.f, s1 = 0.f;
        #pragma unroll
        for (int k = 0; k < 16; k++) {
            const int xi = sub * 16 + k;
            const float v = sm[ch * 65 + xi] * invn[xi];
            if (lab[xi] == 0) s0 += v; else s1 += v;
        }
        s0 += __shfl_xor_sync(0xffffffffu, s0, 1);
        s0 += __shfl_xor_sync(0xffffffffu, s0, 2);
        s1 += __shfl_xor_sync(0xffffffffu, s1, 1);
        s1 += __shfl_xor_sync(0xffffffffu, s1, 2);
        if (sub == 0) {
            g_partial[ch * NBLK + blk]             = s0;   // class 0
            g_partial[(C + ch) * NBLK + blk]       = s1;   // class 1
        }
    }
}

__global__ void __launch_bounds__(1024) separate_pass2(float* __restrict__ out)
{
    __shared__ float S[NSLOT];
    const int t    = threadIdx.x;
    const int slot = t >> 3;       // 0..127
    const int part = t & 7;        // 8 partial lanes per slot

    // 32 independent loads per thread, fully unrolled (high MLP).
    const float* p = g_partial + slot * NBLK + part;
    float s = 0.f;
    #pragma unroll
    for (int i = 0; i < 32; i++)
        s += p[8 * i];

    // 8-way reduce within adjacent lanes.
    s += __shfl_xor_sync(0xffffffffu, s, 1);
    s += __shfl_xor_sync(0xffffffffu, s, 2);
    s += __shfl_xor_sync(0xffffffffu, s, 4);
    if (part == 0) S[slot] = s;
    __syncthreads();

    if (t < 32) {
        // dot(S0, S1): S0 = slots 0..63, S1 = slots 64..127.
        float d = S[t] * S[C + t] + S[t + 32] * S[C + t + 32];
        #pragma unroll
        for (int o = 16; o > 0; o >>= 1)
            d += __shfl_down_sync(0xffffffffu, d, o);
        if (t == 0)
            out[0] = d * (2.0f / (NTOT * NTOT));
    }
}

extern "C" void kernel_launch(void* const* d_in, const int* in_sizes, int n_in,
                              void* d_out, int out_size)
{
    const float* feat  = (const float*)d_in[0];
    const int*   label = (const int*)d_in[1];
    float*       out   = (float*)d_out;

    (void)in_sizes; (void)n_in; (void)out_size;

    separate_pass1<<<dim3(X, B), 256>>>(feat, label);
    separate_pass2<<<1, 1024>>>(out);
}

// round 3
// speedup vs baseline: 1.1936x; 1.1936x over previous
#include <cuda_runtime.h>

// SeparateLoss: mean over the N x N cosine-similarity matrix masked by
// label inequality. Binary labels => (2/N^2) * dot(S0, S1),
// Sk = sum of L2-normalized feature rows with label k.
//
// feat [4, 64, 128, 128] f32, label [4, 1, 128, 128] i32.
// Nearest 128->64 picks even indices. N = 16384, C = 64.
//
// Single fused kernel: 256 blocks compute per-row class/channel partial
// sums; the last block to arrive (int-atomic ticket) reduces all partials
// in a FIXED order (bitwise-deterministic result) and writes the scalar.

#define B 4
#define C 64
#define H 128
#define W 128
#define X 64                       // output spatial size
#define NBLK (B * X)               // 256 blocks
#define NSLOT (2 * C)              // 128 slots (class, channel)
#define NTOT 16384.0f

// slot-major: g_partial[slot * NBLK + blk]. Fully rewritten every launch.
__device__ __align__(16) float g_partial[NSLOT * NBLK];
__device__ int g_ticket = 0;       // reset to 0 by the last block each launch

__global__ void __launch_bounds__(256) separate_fused(
    const float* __restrict__ feat, const int* __restrict__ label,
    float* __restrict__ out)
{
    __shared__ float sm[C * 65];   // [ch][xi], padded stride
    __shared__ float invn[X];
    __shared__ int   lab[X];
    __shared__ int   is_last;

    const int b   = blockIdx.y;
    const int yi  = blockIdx.x;
    const int y   = yi * 2;        // nearest source row
    const int tid = threadIdx.x;
    const int blk = b * X + yi;

    const float* fb = feat + (size_t)b * C * H * W + (size_t)y * W;

    // ---- Stage tile via float4 (even x = .x/.z), 8 loads per thread ----
    #pragma unroll
    for (int i = tid; i < C * (W / 4); i += 256) {
        const int ch = i >> 5;
        const int xj = i & 31;
        const float4 v = reinterpret_cast<const float4*>(fb + (size_t)ch * (H * W))[xj];
        sm[ch * 65 + 2 * xj]     = v.x;
        sm[ch * 65 + 2 * xj + 1] = v.z;
    }
    if (tid < X) lab[tid] = label[b * (H * W) + y * W + tid * 2];
    __syncthreads();

    // ---- Inverse norms: 4 lanes per position, 16 channels each ----
    {
        const int xi = tid >> 2;
        const int q  = tid & 3;
        float s = 0.f;
        #pragma unroll
        for (int k = 0; k < 16; k++) {
            const float v = sm[(q * 16 + k) * 65 + xi];
            s += v * v;
        }
        s += __shfl_xor_sync(0xffffffffu, s, 1);
        s += __shfl_xor_sync(0xffffffffu, s, 2);
        if (q == 0) invn[xi] = 1.0f / fmaxf(sqrtf(s), 1e-12f);
    }
    __syncthreads();

    // ---- Class sums: 4 lanes per channel, 16 positions each ----
    {
        const int ch  = tid >> 2;
        const int sub = tid & 3;
        float s0 = 0.f, s1 = 0.f;
        #pragma unroll
        for (int k = 0; k < 16; k++) {
            const int xi = sub * 16 + k;
            const float v = sm[ch * 65 + xi] * invn[xi];
            if (lab[xi] == 0) s0 += v; else s1 += v;
        }
        s0 += __shfl_xor_sync(0xffffffffu, s0, 1);
        s0 += __shfl_xor_sync(0xffffffffu, s0, 2);
        s1 += __shfl_xor_sync(0xffffffffu, s1, 1);
        s1 += __shfl_xor_sync(0xffffffffu, s1, 2);
        if (sub == 0) {
            g_partial[ch * NBLK + blk]       = s0;   // class 0
            g_partial[(C + ch) * NBLK + blk] = s1;   // class 1
        }
    }

    // ---- Last-block reduction (deterministic order) ----
    __threadfence();
    if (tid == 0) {
        const int t = atomicAdd(&g_ticket, 1);
        is_last = (t == NBLK - 1);
    }
    __syncthreads();
    if (!is_last) return;

    __shared__ float S[NSLOT];
    {
        // 2 threads per slot, 32 float4 (L2-resident) each, fully unrolled.
        const int slot = tid >> 1;
        const int part = tid & 1;
        const float4* p =
            reinterpret_cast<const float4*>(g_partial + slot * NBLK) + part * 32;
        float s = 0.f;
        #pragma unroll
        for (int i = 0; i < 32; i++) {
            const float4 v = p[i];
            s += (v.x + v.y) + (v.z + v.w);
        }
        s += __shfl_xor_sync(0xffffffffu, s, 1);
        if (part == 0) S[slot] = s;
    }
    __syncthreads();

    if (tid < 32) {
        // dot(S0, S1): S0 = slots 0..63, S1 = slots 64..127.
        float d = S[tid] * S[C + tid] + S[tid + 32] * S[C + tid + 32];
        #pragma unroll
        for (int o = 16; o > 0; o >>= 1)
            d += __shfl_down_sync(0xffffffffu, d, o);
        if (tid == 0) {
            out[0] = d * (2.0f / (NTOT * NTOT));
            g_ticket = 0;          // ready for next graph replay
        }
    }
}

extern "C" void kernel_launch(void* const* d_in, const int* in_sizes, int n_in,
                              void* d_out, int out_size)
{
    const float* feat  = (const float*)d_in[0];
    const int*   label = (const int*)d_in[1];
    float*       out   = (float*)d_out;

    (void)in_sizes; (void)n_in; (void)out_size;

    separate_fused<<<dim3(X, B), 256>>>(feat, label, out);
}